// round 1
// baseline (speedup 1.0000x reference)
#include <cuda_runtime.h>

#define NN   131072
#define KK   27
#define FIN  3
#define FOUT 32
#define EPSQ 1e-5f

// 16 MB intermediate h buffer (allocation-free scratch)
__device__ float g_h[NN * FOUT];

// ---- packed f32x2 helpers (sm_103a) ----
__device__ __forceinline__ unsigned long long pack2(float v) {
    unsigned long long r;
    unsigned int u = __float_as_uint(v);
    asm("mov.b64 %0, {%1, %1};" : "=l"(r) : "r"(u));
    return r;
}
__device__ __forceinline__ void fma2(unsigned long long& d, unsigned long long a,
                                     unsigned long long b) {
    asm("fma.rn.f32x2 %0, %1, %2, %0;" : "+l"(d) : "l"(a), "l"(b));
}
__device__ __forceinline__ float2 unpack2(unsigned long long v) {
    unsigned int lo, hi;
    asm("mov.b64 {%0, %1}, %2;" : "=r"(lo), "=r"(hi) : "l"(v));
    return make_float2(__uint_as_float(lo), __uint_as_float(hi));
}

// ============================================================================
// Kernel 1: h = SiLU(BN(einsum(x[nbr], w1)))  -> g_h
// one thread per node, 16 f32x2 accumulators (32 outputs)
// ============================================================================
__global__ __launch_bounds__(256) void k1(const float* __restrict__ x,
                                          const int* __restrict__ nbr,
                                          const float* __restrict__ w1,
                                          const float* __restrict__ gam,
                                          const float* __restrict__ bet,
                                          const float* __restrict__ mean,
                                          const float* __restrict__ var) {
    __shared__ float w1s[KK * FIN * FOUT];   // 10.1 KB
    __shared__ float s_s[FOUT], s_t[FOUT];
    int tid = threadIdx.x;
    for (int i = tid; i < KK * FIN * FOUT; i += 256) w1s[i] = w1[i];
    if (tid < FOUT) {
        float sc = gam[tid] * rsqrtf(var[tid] + EPSQ);
        s_s[tid] = sc;
        s_t[tid] = bet[tid] - mean[tid] * sc;
    }
    __syncthreads();

    int n = blockIdx.x * 256 + tid;
    unsigned long long acc[16];
#pragma unroll
    for (int p = 0; p < 16; p++) acc[p] = 0ull;

    const int* nrow = nbr + (long)n * KK;
#pragma unroll 1
    for (int k = 0; k < KK; k++) {
        int idx = nrow[k];
        const float* xr = x + (long)idx * 3;
        float x0 = xr[0], x1 = xr[1], x2 = xr[2];
        const float* w = w1s + k * (FIN * FOUT);
        unsigned long long h0 = pack2(x0), h1 = pack2(x1), h2 = pack2(x2);
#pragma unroll
        for (int p = 0; p < 16; p++)
            fma2(acc[p], h0, *(const unsigned long long*)(w + 2 * p));
#pragma unroll
        for (int p = 0; p < 16; p++)
            fma2(acc[p], h1, *(const unsigned long long*)(w + FOUT + 2 * p));
#pragma unroll
        for (int p = 0; p < 16; p++)
            fma2(acc[p], h2, *(const unsigned long long*)(w + 2 * FOUT + 2 * p));
    }

    float* hr = g_h + (long)n * FOUT;
#pragma unroll
    for (int q = 0; q < 8; q++) {
        float2 v0 = unpack2(acc[2 * q]);
        float2 v1 = unpack2(acc[2 * q + 1]);
        float r[4] = {v0.x, v0.y, v1.x, v1.y};
        float4 res;
        float* rp = &res.x;
#pragma unroll
        for (int j = 0; j < 4; j++) {
            int o = q * 4 + j;
            float v = r[j] * s_s[o] + s_t[o];
            // SiLU
            rp[j] = v / (1.0f + __expf(-v));
        }
        ((float4*)hr)[q] = res;
    }
}

// ============================================================================
// Kernel 2: x_out = einsum(h[nbr], w2); fused = x_out + relu(BN(z @ mlp_w + b))
// T=2 nodes/thread, 256 threads/CTA -> 512 nodes/CTA, grid 256.
// Full w2 (108 KB) in dynamic shared memory (2 CTAs/SM).
// ============================================================================
#define SMEM2 (KK * FOUT * FOUT * 4 + 1024)   // 110592 + 1024 bytes

extern "C" __global__ __launch_bounds__(256)
void k2(const float* __restrict__ z_feats, const int* __restrict__ nbr,
        const float* __restrict__ w2, const float* __restrict__ mlp_w,
        const float* __restrict__ mlp_b, const float* __restrict__ mg,
        const float* __restrict__ mbeta, const float* __restrict__ mm,
        const float* __restrict__ mv, float* __restrict__ out) {
    extern __shared__ float smem[];
    float* w2s = smem;                       // 27648 floats
    float* mws = smem + KK * FOUT * FOUT;    // 96
    float* mscale = mws + 96;                // 32
    float* mbias = mscale + 32;              // 32

    int tid = threadIdx.x;
    {
        const float4* src = (const float4*)w2;
        float4* dst = (float4*)w2s;
        for (int i = tid; i < (KK * FOUT * FOUT) / 4; i += 256) dst[i] = src[i];
        for (int i = tid; i < 96; i += 256) mws[i] = mlp_w[i];
        if (tid < FOUT) {
            float sc = mg[tid] * rsqrtf(mv[tid] + EPSQ);
            mscale[tid] = sc;
            mbias[tid] = (mlp_b[tid] - mm[tid]) * sc + mbeta[tid];
        }
    }
    __syncthreads();

    int n0 = blockIdx.x * 512 + tid;
    int n1 = n0 + 256;

    unsigned long long a0[16], a1[16];
#pragma unroll
    for (int p = 0; p < 16; p++) { a0[p] = 0ull; a1[p] = 0ull; }

    const int* r0 = nbr + (long)n0 * KK;
    const int* r1 = nbr + (long)n1 * KK;

#pragma unroll 1
    for (int k = 0; k < KK; k++) {
        int i0 = r0[k];
        int i1 = r1[k];
        const float4* h0 = (const float4*)(g_h + (long)i0 * FOUT);
        const float4* h1 = (const float4*)(g_h + (long)i1 * FOUT);
        const float* w = w2s + k * (FOUT * FOUT);
#pragma unroll
        for (int c = 0; c < 8; c++) {
            float4 v0 = h0[c];
            float4 v1 = h1[c];
            const float* e0 = &v0.x;
            const float* e1 = &v1.x;
#pragma unroll
            for (int j = 0; j < 4; j++) {
                int f = c * 4 + j;
                unsigned long long p0 = pack2(e0[j]);
                unsigned long long p1 = pack2(e1[j]);
                const unsigned long long* wr =
                    (const unsigned long long*)(w + f * FOUT);
#pragma unroll
                for (int p = 0; p < 16; p++) {
                    unsigned long long wv = wr[p];
                    fma2(a0[p], p0, wv);
                    fma2(a1[p], p1, wv);
                }
            }
        }
    }

    // epilogue: point branch + dual write
#pragma unroll
    for (int t = 0; t < 2; t++) {
        int n = t == 0 ? n0 : n1;
        unsigned long long* a = t == 0 ? a0 : a1;
        float zf0 = z_feats[(long)n * 3 + 0];
        float zf1 = z_feats[(long)n * 3 + 1];
        float zf2 = z_feats[(long)n * 3 + 2];
        float* o0 = out + (size_t)n * FOUT;
        float* o1 = out + (size_t)NN * FOUT + (size_t)n * FOUT;
#pragma unroll
        for (int q = 0; q < 8; q++) {
            float2 v0 = unpack2(a[2 * q]);
            float2 v1 = unpack2(a[2 * q + 1]);
            float r[4] = {v0.x, v0.y, v1.x, v1.y};
            float4 res;
            float* rp = &res.x;
#pragma unroll
            for (int j = 0; j < 4; j++) {
                int o = q * 4 + j;
                float zp = zf0 * mws[o] + zf1 * mws[32 + o] + zf2 * mws[64 + o];
                float z = zp * mscale[o] + mbias[o];
                z = fmaxf(z, 0.0f);
                rp[j] = r[j] + z;
            }
            ((float4*)o0)[q] = res;
            ((float4*)o1)[q] = res;
        }
    }
}

// ============================================================================
extern "C" void kernel_launch(void* const* d_in, const int* in_sizes, int n_in,
                              void* d_out, int out_size) {
    const float* x_feats   = (const float*)d_in[0];
    const float* z_feats   = (const float*)d_in[1];
    const int*   nbr_idx   = (const int*)d_in[2];
    const float* w1        = (const float*)d_in[3];
    const float* bn1_gamma = (const float*)d_in[4];
    const float* bn1_beta  = (const float*)d_in[5];
    const float* bn1_mean  = (const float*)d_in[6];
    const float* bn1_var   = (const float*)d_in[7];
    const float* w2        = (const float*)d_in[8];
    const float* mlp_w     = (const float*)d_in[9];
    const float* mlp_b     = (const float*)d_in[10];
    const float* mlp_gamma = (const float*)d_in[11];
    const float* mlp_beta  = (const float*)d_in[12];
    const float* mlp_mean  = (const float*)d_in[13];
    const float* mlp_var   = (const float*)d_in[14];
    float* out = (float*)d_out;

    cudaFuncSetAttribute(k2, cudaFuncAttributeMaxDynamicSharedMemorySize, SMEM2);

    k1<<<NN / 256, 256>>>(x_feats, nbr_idx, w1, bn1_gamma, bn1_beta, bn1_mean,
                          bn1_var);
    k2<<<NN / 512, 256, SMEM2>>>(z_feats, nbr_idx, w2, mlp_w, mlp_b, mlp_gamma,
                                 mlp_beta, mlp_mean, mlp_var, out);
}

// round 2
// speedup vs baseline: 1.1485x; 1.1485x over previous
#include <cuda_runtime.h>

#define NN   131072
#define KK   27
#define FIN  3
#define FOUT 32
#define EPSQ 1e-5f

// scratch (allocation-free): 16 MB h buffer + 2 MB padded x
__device__ float  g_h[NN * FOUT];
__device__ float4 g_x4[NN];

// ---- packed f32x2 helpers (sm_103a) ----
__device__ __forceinline__ unsigned long long pack2(float v) {
    unsigned long long r;
    unsigned int u = __float_as_uint(v);
    asm("mov.b64 %0, {%1, %1};" : "=l"(r) : "r"(u));
    return r;
}
__device__ __forceinline__ void fma2(unsigned long long& d, unsigned long long a,
                                     unsigned long long b) {
    asm("fma.rn.f32x2 %0, %1, %2, %0;" : "+l"(d) : "l"(a), "l"(b));
}
__device__ __forceinline__ float2 unpack2(unsigned long long v) {
    unsigned int lo, hi;
    asm("mov.b64 {%0, %1}, %2;" : "=r"(lo), "=r"(hi) : "l"(v));
    return make_float2(__uint_as_float(lo), __uint_as_float(hi));
}

// ============================================================================
// k0: pack x [N,3] -> float4 table (16B-aligned rows => 1 LDG.128 per gather)
// ============================================================================
__global__ __launch_bounds__(256) void k0(const float* __restrict__ x) {
    int n = blockIdx.x * 256 + threadIdx.x;
    const float* r = x + (long)n * 3;
    g_x4[n] = make_float4(r[0], r[1], r[2], 0.0f);
}

// ============================================================================
// k1: h = SiLU(BN(einsum(x4[nbr], w1))) -> g_h
// nbr slice staged coalescedly into smem; x gathered as single float4.
// ============================================================================
__global__ __launch_bounds__(256) void k1(const int* __restrict__ nbr,
                                          const float* __restrict__ w1,
                                          const float* __restrict__ gam,
                                          const float* __restrict__ bet,
                                          const float* __restrict__ mean,
                                          const float* __restrict__ var) {
    __shared__ float w1s[KK * FIN * FOUT];     // 2592 floats
    __shared__ int   idx_s[256 * KK];          // 6912 ints (27.6 KB)
    __shared__ float s_s[FOUT], s_t[FOUT];
    int tid = threadIdx.x;

    {   // coalesced weight + index staging
        const float4* wsrc = (const float4*)w1;
        float4* wdst = (float4*)w1s;
        for (int i = tid; i < (KK * FIN * FOUT) / 4; i += 256) wdst[i] = wsrc[i];
        const int4* isrc = (const int4*)(nbr + (size_t)blockIdx.x * 256 * KK);
        int4* idst = (int4*)idx_s;
        for (int i = tid; i < (256 * KK) / 4; i += 256) idst[i] = isrc[i];
        if (tid < FOUT) {
            float sc = gam[tid] * rsqrtf(var[tid] + EPSQ);
            s_s[tid] = sc;
            s_t[tid] = bet[tid] - mean[tid] * sc;
        }
    }
    __syncthreads();

    unsigned long long acc[16];
#pragma unroll
    for (int p = 0; p < 16; p++) acc[p] = 0ull;

#pragma unroll 1
    for (int k = 0; k < KK; k++) {
        int idx = idx_s[tid * KK + k];
        float4 xv = g_x4[idx];
        unsigned long long p0 = pack2(xv.x), p1 = pack2(xv.y), p2 = pack2(xv.z);
        const float* w = w1s + k * (FIN * FOUT);
        const ulonglong2* w0 = (const ulonglong2*)(w);
        const ulonglong2* w1p = (const ulonglong2*)(w + FOUT);
        const ulonglong2* w2p = (const ulonglong2*)(w + 2 * FOUT);
#pragma unroll
        for (int q = 0; q < 8; q++) {
            ulonglong2 a = w0[q];
            fma2(acc[2 * q], p0, a.x);
            fma2(acc[2 * q + 1], p0, a.y);
        }
#pragma unroll
        for (int q = 0; q < 8; q++) {
            ulonglong2 a = w1p[q];
            fma2(acc[2 * q], p1, a.x);
            fma2(acc[2 * q + 1], p1, a.y);
        }
#pragma unroll
        for (int q = 0; q < 8; q++) {
            ulonglong2 a = w2p[q];
            fma2(acc[2 * q], p2, a.x);
            fma2(acc[2 * q + 1], p2, a.y);
        }
    }

    int n = blockIdx.x * 256 + tid;
    float* hr = g_h + (long)n * FOUT;
#pragma unroll
    for (int q = 0; q < 8; q++) {
        float2 v0 = unpack2(acc[2 * q]);
        float2 v1 = unpack2(acc[2 * q + 1]);
        float r[4] = {v0.x, v0.y, v1.x, v1.y};
        float4 res;
        float* rp = &res.x;
#pragma unroll
        for (int j = 0; j < 4; j++) {
            int o = q * 4 + j;
            float v = r[j] * s_s[o] + s_t[o];
            rp[j] = v / (1.0f + __expf(-v));   // SiLU
        }
        ((float4*)hr)[q] = res;
    }
}

// ============================================================================
// k2: x_out = einsum(h[nbr], w2); out = x_out + relu(BN(z@mlp_w+b)) (x2 copies)
// CTA = 256 threads, 512 nodes (2/thread). Per-k pipeline:
//   stage: coalesced gather of 512 h-rows (4 rows per LDG.128) -> h_s[512][36]
//          + w2[k] (4 KB) -> w_s
//   compute: LDS.128 h + LDS.128 w (ulonglong2), f32x2 FMA
// smem ~78.5 KB -> 2 CTAs/SM, 16 warps/SM.
// ============================================================================
#define NODES  512
#define HPAD   36
#define SMEM2  (NODES * HPAD * 4 + 1024 * 4 + (96 + 32 + 32) * 4 + 64)

extern "C" __global__ void __launch_bounds__(256, 2)
k2(const float* __restrict__ z_feats, const int* __restrict__ nbr,
   const float* __restrict__ w2, const float* __restrict__ mlp_w,
   const float* __restrict__ mlp_b, const float* __restrict__ mg,
   const float* __restrict__ mbeta, const float* __restrict__ mm,
   const float* __restrict__ mv, float* __restrict__ out) {
    extern __shared__ float smem[];
    float* h_s    = smem;                    // 512*36 floats
    float* w_s    = smem + NODES * HPAD;     // 1024 floats
    float* mws    = w_s + 1024;              // 96
    float* mscale = mws + 96;                // 32
    float* mbias  = mscale + 32;             // 32

    int tid = threadIdx.x;
    int base = blockIdx.x * NODES;

    for (int i = tid; i < 96; i += 256) mws[i] = mlp_w[i];
    if (tid < FOUT) {
        float sc = mg[tid] * rsqrtf(mv[tid] + EPSQ);
        mscale[tid] = sc;
        mbias[tid] = (mlp_b[tid] - mm[tid]) * sc + mbeta[tid];
    }

    unsigned long long a0[16], a1[16];
#pragma unroll
    for (int p = 0; p < 16; p++) { a0[p] = 0ull; a1[p] = 0ull; }

#pragma unroll 1
    for (int k = 0; k < KK; k++) {
        __syncthreads();   // previous iteration's readers done
        // stage w2[k] (coalesced, 1 float4/thread)
        ((float4*)w_s)[tid] = ((const float4*)(w2 + k * 1024))[tid];
        // stage 512 gathered h rows: chunk c = tid + 256*i; row=c>>3, ch=c&7
        // => warp covers 4 rows x 8 chunks, each LDG.128 touches 4 lines.
#pragma unroll
        for (int i = 0; i < 16; i += 2) {   // two chunks per step limits reg use
#pragma unroll
            for (int u = 0; u < 2; u++) {
                int c = tid + (i + u) * 256;
                int row = c >> 3, ch = c & 7;
                int idx = nbr[(size_t)(base + row) * KK + k];
                float4 v = *(const float4*)(g_h + (size_t)idx * FOUT + ch * 4);
                *(float4*)(h_s + row * HPAD + ch * 4) = v;
            }
        }
        __syncthreads();

        const float4* h0 = (const float4*)(h_s + tid * HPAD);
        const float4* h1 = (const float4*)(h_s + (tid + 256) * HPAD);
#pragma unroll
        for (int c = 0; c < 8; c++) {
            float4 v0 = h0[c];
            float4 v1 = h1[c];
            const float* e0 = &v0.x;
            const float* e1 = &v1.x;
#pragma unroll
            for (int j = 0; j < 4; j++) {
                int f = c * 4 + j;
                unsigned long long p0 = pack2(e0[j]);
                unsigned long long p1 = pack2(e1[j]);
                const ulonglong2* wr = (const ulonglong2*)(w_s + f * FOUT);
#pragma unroll
                for (int q = 0; q < 8; q++) {
                    ulonglong2 wv = wr[q];
                    fma2(a0[2 * q],     p0, wv.x);
                    fma2(a0[2 * q + 1], p0, wv.y);
                    fma2(a1[2 * q],     p1, wv.x);
                    fma2(a1[2 * q + 1], p1, wv.y);
                }
            }
        }
    }

    // epilogue: point branch + dual write
#pragma unroll
    for (int t = 0; t < 2; t++) {
        int n = base + tid + t * 256;
        unsigned long long* a = t == 0 ? a0 : a1;
        float zf0 = z_feats[(long)n * 3 + 0];
        float zf1 = z_feats[(long)n * 3 + 1];
        float zf2 = z_feats[(long)n * 3 + 2];
        float* o0 = out + (size_t)n * FOUT;
        float* o1 = out + (size_t)NN * FOUT + (size_t)n * FOUT;
#pragma unroll
        for (int q = 0; q < 8; q++) {
            float2 v0 = unpack2(a[2 * q]);
            float2 v1 = unpack2(a[2 * q + 1]);
            float r[4] = {v0.x, v0.y, v1.x, v1.y};
            float4 res;
            float* rp = &res.x;
#pragma unroll
            for (int j = 0; j < 4; j++) {
                int o = q * 4 + j;
                float zp = zf0 * mws[o] + zf1 * mws[32 + o] + zf2 * mws[64 + o];
                float z = zp * mscale[o] + mbias[o];
                rp[j] = r[j] + fmaxf(z, 0.0f);
            }
            ((float4*)o0)[q] = res;
            ((float4*)o1)[q] = res;
        }
    }
}

// ============================================================================
extern "C" void kernel_launch(void* const* d_in, const int* in_sizes, int n_in,
                              void* d_out, int out_size) {
    const float* x_feats   = (const float*)d_in[0];
    const float* z_feats   = (const float*)d_in[1];
    const int*   nbr_idx   = (const int*)d_in[2];
    const float* w1        = (const float*)d_in[3];
    const float* bn1_gamma = (const float*)d_in[4];
    const float* bn1_beta  = (const float*)d_in[5];
    const float* bn1_mean  = (const float*)d_in[6];
    const float* bn1_var   = (const float*)d_in[7];
    const float* w2        = (const float*)d_in[8];
    const float* mlp_w     = (const float*)d_in[9];
    const float* mlp_b     = (const float*)d_in[10];
    const float* mlp_gamma = (const float*)d_in[11];
    const float* mlp_beta  = (const float*)d_in[12];
    const float* mlp_mean  = (const float*)d_in[13];
    const float* mlp_var   = (const float*)d_in[14];
    float* out = (float*)d_out;

    cudaFuncSetAttribute(k2, cudaFuncAttributeMaxDynamicSharedMemorySize, SMEM2);

    k0<<<NN / 256, 256>>>(x_feats);
    k1<<<NN / 256, 256>>>(nbr_idx, w1, bn1_gamma, bn1_beta, bn1_mean, bn1_var);
    k2<<<NN / NODES, 256, SMEM2>>>(z_feats, nbr_idx, w2, mlp_w, mlp_b,
                                   mlp_gamma, mlp_beta, mlp_mean, mlp_var, out);
}